// round 1
// baseline (speedup 1.0000x reference)
#include <cuda_runtime.h>
#include <math.h>
#include <stdint.h>

// ---------------------------------------------------------------------------
// MultiviewDecoderBlock (Vx=8, Vy=8, B=4, N=196, C=768, H=12, DH=64, M=4)
// fp32 reference-accurate pipeline, multi-kernel, graph-capturable.
// ---------------------------------------------------------------------------

constexpr int VX = 8, VY = 8, BB = 4, NN = 196, CC = 768, HH = 12, DHH = 64, MV = 4;
constexpr int HID = 4 * CC;            // 3072
constexpr int VB = VX * BB;            // 32
constexpr int T  = VB * NN;            // 6272 tokens (x)
constexpr int TT = VX * MV * BB * NN;  // 25088 tokens (cross out)
constexpr int PSELF  = VB * HH;            // 384
constexpr int PCROSS = VX * MV * BB * HH;  // 1536
constexpr float ATTN_SCALE = 0.125f;       // 64^-0.5

// -------------------------- device scratch ---------------------------------
__device__ float g_x  [T * CC];
__device__ float g_h  [T * CC];
__device__ float g_yn [T * CC];
__device__ float g_qkv[T * 3 * CC];
__device__ float g_q  [T * CC];
__device__ float g_k  [T * CC];
__device__ float g_v  [T * CC];
__device__ float g_o  [T * CC];
__device__ float g_big [TT * CC];  // cross-attn output (25088 x 768)
__device__ float g_big2[TT * CC];  // cross proj out; reused as MLP hidden (6272x3072, same size)
__device__ float g_S[(size_t)PCROSS * NN * NN];  // attention scores (236 MB)

// ----------------------------- utility -------------------------------------
__global__ void copy_kernel(const float* __restrict__ src, float* __restrict__ dst, int n) {
    int i = blockIdx.x * blockDim.x + threadIdx.x;
    if (i < n) dst[i] = src[i];
}

// One block per row (C=768), 256 threads, 3 elems/thread.
__global__ void layernorm_kernel(const float* __restrict__ in,
                                 const float* __restrict__ w,
                                 const float* __restrict__ b,
                                 float* __restrict__ out) {
    int row = blockIdx.x;
    const float* xr = in + (size_t)row * CC;
    float* orow = out + (size_t)row * CC;
    int tid = threadIdx.x;
    float v0 = xr[tid], v1 = xr[tid + 256], v2 = xr[tid + 512];
    float s  = v0 + v1 + v2;
    float sq = v0 * v0 + v1 * v1 + v2 * v2;
    #pragma unroll
    for (int off = 16; off; off >>= 1) {
        s  += __shfl_xor_sync(0xffffffffu, s, off);
        sq += __shfl_xor_sync(0xffffffffu, sq, off);
    }
    __shared__ float red[2][8];
    int warp = tid >> 5, lane = tid & 31;
    if (lane == 0) { red[0][warp] = s; red[1][warp] = sq; }
    __syncthreads();
    float ts = 0.f, tsq = 0.f;
    #pragma unroll
    for (int i = 0; i < 8; i++) { ts += red[0][i]; tsq += red[1][i]; }
    float mu = ts * (1.0f / CC);
    float var = tsq * (1.0f / CC) - mu * mu;
    float rstd = rsqrtf(var + 1e-5f);
    orow[tid]       = (v0 - mu) * rstd * w[tid]       + b[tid];
    orow[tid + 256] = (v1 - mu) * rstd * w[tid + 256] + b[tid + 256];
    orow[tid + 512] = (v2 - mu) * rstd * w[tid + 512] + b[tid + 512];
}

// ------------------------ dense SGEMM (C = A @ B^T) -------------------------
// A: (M,K) row-major, B: (N,K) row-major. M%128==0, N%128==0, K%8==0.
// EPI: 0=store, 1=+bias, 2=+bias+residual, 3=+bias+gelu(exact)
template<int EPI>
__global__ void __launch_bounds__(256) sgemm_nt(
    const float* __restrict__ A, const float* __restrict__ Bw,
    const float* __restrict__ bias, const float* __restrict__ res,
    float* __restrict__ C, int Mdim, int Ndim, int Kdim)
{
    __shared__ float As[2][8][128];
    __shared__ float Bs[2][8][128];
    const int tid = threadIdx.x;
    const int bm = blockIdx.y * 128, bn = blockIdx.x * 128;
    const int lrow = tid >> 1;
    const int lk   = (tid & 1) * 4;
    const float* Ag = A  + (size_t)(bm + lrow) * Kdim + lk;
    const float* Bg = Bw + (size_t)(bn + lrow) * Kdim + lk;
    const int tr = (tid >> 4) * 8;
    const int tc = (tid & 15) * 8;

    float acc[8][8];
    #pragma unroll
    for (int i = 0; i < 8; i++)
        #pragma unroll
        for (int j = 0; j < 8; j++) acc[i][j] = 0.f;

    float4 a4 = *(const float4*)Ag;
    float4 b4 = *(const float4*)Bg;
    As[0][lk + 0][lrow] = a4.x; As[0][lk + 1][lrow] = a4.y;
    As[0][lk + 2][lrow] = a4.z; As[0][lk + 3][lrow] = a4.w;
    Bs[0][lk + 0][lrow] = b4.x; Bs[0][lk + 1][lrow] = b4.y;
    Bs[0][lk + 2][lrow] = b4.z; Bs[0][lk + 3][lrow] = b4.w;
    __syncthreads();

    const int nk = Kdim >> 3;
    for (int kt = 0; kt < nk; ++kt) {
        const int cur = kt & 1;
        if (kt + 1 < nk) {
            a4 = *(const float4*)(Ag + (size_t)(kt + 1) * 8);
            b4 = *(const float4*)(Bg + (size_t)(kt + 1) * 8);
        }
        #pragma unroll
        for (int k = 0; k < 8; k++) {
            float ar[8], br[8];
            *(float4*)(ar)     = *(const float4*)&As[cur][k][tr];
            *(float4*)(ar + 4) = *(const float4*)&As[cur][k][tr + 4];
            *(float4*)(br)     = *(const float4*)&Bs[cur][k][tc];
            *(float4*)(br + 4) = *(const float4*)&Bs[cur][k][tc + 4];
            #pragma unroll
            for (int i = 0; i < 8; i++)
                #pragma unroll
                for (int j = 0; j < 8; j++)
                    acc[i][j] += ar[i] * br[j];
        }
        if (kt + 1 < nk) {
            const int nxt = cur ^ 1;
            As[nxt][lk + 0][lrow] = a4.x; As[nxt][lk + 1][lrow] = a4.y;
            As[nxt][lk + 2][lrow] = a4.z; As[nxt][lk + 3][lrow] = a4.w;
            Bs[nxt][lk + 0][lrow] = b4.x; Bs[nxt][lk + 1][lrow] = b4.y;
            Bs[nxt][lk + 2][lrow] = b4.z; Bs[nxt][lk + 3][lrow] = b4.w;
            __syncthreads();
        }
    }

    #pragma unroll
    for (int i = 0; i < 8; i++) {
        const size_t row = (size_t)(bm + tr + i);
        float o[8];
        #pragma unroll
        for (int j = 0; j < 8; j++) {
            const int col = bn + tc + j;
            float vv = acc[i][j];
            if (EPI >= 1) vv += bias[col];
            if (EPI == 2) vv += res[row * Ndim + col];
            if (EPI == 3) vv = 0.5f * vv * (1.0f + erff(vv * 0.70710678118654752f));
            o[j] = vv;
        }
        float* cp = C + row * Ndim + bn + tc;
        *(float4*)(cp)     = *(float4*)(o);
        *(float4*)(cp + 4) = *(float4*)(o + 4);
    }
}

// ----------------------- batched attention: S = scale*Q K^T -----------------
// Tiles 64x64, K=64 fully resident. grid (4,4,P), 256 threads.
template<bool CROSS>
__global__ void __launch_bounds__(256) attn_scores_kernel(
    const float* __restrict__ Qsrc, const float* __restrict__ Ksrc,
    const int* __restrict__ rel, float* __restrict__ S)
{
    __shared__ float Qs[64][DHH + 1];
    __shared__ float Ks[64][DHH + 1];
    const int p = blockIdx.z;
    const float *qp, *kp;
    int qrs, krs;
    if (!CROSS) {
        int vb = p / HH, h = p - vb * HH;
        qp = Qsrc + (size_t)vb * NN * 3 * CC + h * DHH;
        kp = Qsrc + (size_t)vb * NN * 3 * CC + CC + h * DHH;
        qrs = 3 * CC; krs = 3 * CC;
    } else {
        int h = p % HH; int rest = p / HH;
        int b = rest % BB; rest /= BB;
        int m = rest % MV; int v = rest / MV;
        int vy = rel[v * MV + m];
        qp = Qsrc + ((size_t)(v * BB + b) * NN) * CC + h * DHH; qrs = CC;
        kp = Ksrc + ((size_t)(vy * BB + b) * NN) * CC + h * DHH; krs = CC;
    }
    const int m0 = blockIdx.y * 64, n0 = blockIdx.x * 64;
    const int tid = threadIdx.x;

    #pragma unroll
    for (int it = 0; it < 4; ++it) {
        int idx = tid + 256 * it;
        int row = idx >> 4, k4 = (idx & 15) * 4;
        float4 qv = make_float4(0.f, 0.f, 0.f, 0.f);
        float4 kv = make_float4(0.f, 0.f, 0.f, 0.f);
        if (m0 + row < NN) qv = *(const float4*)(qp + (size_t)(m0 + row) * qrs + k4);
        if (n0 + row < NN) kv = *(const float4*)(kp + (size_t)(n0 + row) * krs + k4);
        Qs[row][k4 + 0] = qv.x; Qs[row][k4 + 1] = qv.y; Qs[row][k4 + 2] = qv.z; Qs[row][k4 + 3] = qv.w;
        Ks[row][k4 + 0] = kv.x; Ks[row][k4 + 1] = kv.y; Ks[row][k4 + 2] = kv.z; Ks[row][k4 + 3] = kv.w;
    }
    __syncthreads();

    const int ty = tid >> 4, tx = tid & 15;
    float acc[4][4];
    #pragma unroll
    for (int i = 0; i < 4; i++)
        #pragma unroll
        for (int j = 0; j < 4; j++) acc[i][j] = 0.f;

    #pragma unroll 16
    for (int k = 0; k < DHH; k++) {
        float a[4], b[4];
        #pragma unroll
        for (int i = 0; i < 4; i++) a[i] = Qs[ty * 4 + i][k];
        #pragma unroll
        for (int j = 0; j < 4; j++) b[j] = Ks[tx * 4 + j][k];
        #pragma unroll
        for (int i = 0; i < 4; i++)
            #pragma unroll
            for (int j = 0; j < 4; j++)
                acc[i][j] += a[i] * b[j];
    }

    float* Sp = S + (size_t)p * NN * NN;
    #pragma unroll
    for (int i = 0; i < 4; i++) {
        int m = m0 + ty * 4 + i;
        if (m >= NN) continue;
        #pragma unroll
        for (int j = 0; j < 4; j++) {
            int n = n0 + tx * 4 + j;
            if (n < NN) Sp[(size_t)m * NN + n] = acc[i][j] * ATTN_SCALE;
        }
    }
}

// ------------------------ softmax over rows of length 196 -------------------
__global__ void softmax_kernel(float* __restrict__ S, int rows) {
    int row = blockIdx.x * blockDim.y + threadIdx.y;
    if (row >= rows) return;
    float* r = S + (size_t)row * NN;
    int lane = threadIdx.x;
    float v[7];
    float mx = -1e30f;
    #pragma unroll
    for (int t = 0; t < 7; t++) {
        int j = lane + 32 * t;
        v[t] = (j < NN) ? r[j] : -1e30f;
        mx = fmaxf(mx, v[t]);
    }
    #pragma unroll
    for (int off = 16; off; off >>= 1) mx = fmaxf(mx, __shfl_xor_sync(0xffffffffu, mx, off));
    float sum = 0.f;
    #pragma unroll
    for (int t = 0; t < 7; t++) { float e = __expf(v[t] - mx); v[t] = e; sum += e; }
    #pragma unroll
    for (int off = 16; off; off >>= 1) sum += __shfl_xor_sync(0xffffffffu, sum, off);
    float inv = 1.0f / sum;
    #pragma unroll
    for (int t = 0; t < 7; t++) {
        int j = lane + 32 * t;
        if (j < NN) r[j] = v[t] * inv;
    }
}

// -------------------------- batched O = P @ V -------------------------------
// M tiles of 64, N=64 (full DH), K streamed in 16-chunks. grid (1,4,P).
template<bool CROSS>
__global__ void __launch_bounds__(256) attn_av_kernel(
    const float* __restrict__ S, const float* __restrict__ Vsrc,
    const int* __restrict__ rel, float* __restrict__ Out)
{
    __shared__ float Ps[64][17];
    __shared__ float Vs[16][DHH];
    const int p = blockIdx.z;
    const float* vp; float* op; int vrs;
    if (!CROSS) {
        int vb = p / HH, h = p % HH;
        vp = Vsrc + (size_t)vb * NN * 3 * CC + 2 * CC + h * DHH; vrs = 3 * CC;
        op = Out + (size_t)vb * NN * CC + h * DHH;
    } else {
        int h = p % HH; int rest = p / HH;
        int b = rest % BB; rest /= BB;
        int m = rest % MV; int v = rest / MV;
        int vy = rel[v * MV + m];
        vp = Vsrc + ((size_t)(vy * BB + b) * NN) * CC + h * DHH; vrs = CC;
        op = Out + ((size_t)(p / HH)) * NN * CC + h * DHH;
    }
    const float* Sp = S + (size_t)p * NN * NN;
    const int m0 = blockIdx.y * 64;
    const int tid = threadIdx.x;
    const int ty = tid >> 4, tx = tid & 15;

    float acc[4][4];
    #pragma unroll
    for (int i = 0; i < 4; i++)
        #pragma unroll
        for (int j = 0; j < 4; j++) acc[i][j] = 0.f;

    for (int kk = 0; kk < NN; kk += 16) {
        {   // load P tile 64x16
            int row = tid >> 2, k4 = (tid & 3) * 4;
            int m = m0 + row;
            float x0 = 0.f, x1 = 0.f, x2 = 0.f, x3 = 0.f;
            if (m < NN) {
                const float* src = Sp + (size_t)m * NN + kk + k4;
                if (kk + k4 + 0 < NN) x0 = src[0];
                if (kk + k4 + 1 < NN) x1 = src[1];
                if (kk + k4 + 2 < NN) x2 = src[2];
                if (kk + k4 + 3 < NN) x3 = src[3];
            }
            Ps[row][k4 + 0] = x0; Ps[row][k4 + 1] = x1;
            Ps[row][k4 + 2] = x2; Ps[row][k4 + 3] = x3;
        }
        {   // load V tile 16x64
            int krow = tid >> 4, d4 = (tid & 15) * 4;
            int kg = kk + krow;
            float4 vv = make_float4(0.f, 0.f, 0.f, 0.f);
            if (kg < NN) vv = *(const float4*)(vp + (size_t)kg * vrs + d4);
            *(float4*)&Vs[krow][d4] = vv;
        }
        __syncthreads();
        #pragma unroll
        for (int k = 0; k < 16; k++) {
            float a[4], b[4];
            #pragma unroll
            for (int i = 0; i < 4; i++) a[i] = Ps[ty * 4 + i][k];
            *(float4*)b = *(const float4*)&Vs[k][tx * 4];
            #pragma unroll
            for (int i = 0; i < 4; i++)
                #pragma unroll
                for (int j = 0; j < 4; j++)
                    acc[i][j] += a[i] * b[j];
        }
        __syncthreads();
    }

    #pragma unroll
    for (int i = 0; i < 4; i++) {
        int m = m0 + ty * 4 + i;
        if (m < NN) {
            float* dst = op + (size_t)m * CC + tx * 4;
            *(float4*)dst = make_float4(acc[i][0], acc[i][1], acc[i][2], acc[i][3]);
        }
    }
}

// ------------------- max-merge over M and residual add ----------------------
__global__ void merge_kernel(const float* __restrict__ proj, float* __restrict__ x) {
    int idx = blockIdx.x * blockDim.x + threadIdx.x;
    if (idx >= T * CC) return;
    int c = idx % CC;
    int n = (idx / CC) % NN;
    int b = (idx / (CC * NN)) % BB;
    int v = idx / (CC * NN * BB);
    size_t base = ((((size_t)v * MV) * BB + b) * NN + n) * CC + c;
    size_t ms = (size_t)BB * NN * CC;
    float mx = proj[base];
    #pragma unroll
    for (int m = 1; m < MV; m++) mx = fmaxf(mx, proj[base + (size_t)m * ms]);
    x[idx] += mx;
}

// ------------------------------- launch -------------------------------------
extern "C" void kernel_launch(void* const* d_in, const int* in_sizes, int n_in,
                              void* d_out, int out_size) {
    // Defensive: detect whether scalar M (index 5, size 1) was materialized.
    int sh = (in_sizes[5] == 1) ? 0 : -1;

    const float* xs  = (const float*)d_in[0];
    const float* ys  = (const float*)d_in[1];
    const int* rel   = (const int*)d_in[4];
    const float* qkv_w = (const float*)d_in[6 + sh];
    const float* ap_w  = (const float*)d_in[7 + sh];
    const float* ap_b  = (const float*)d_in[8 + sh];
    const float* q_w   = (const float*)d_in[9 + sh];
    const float* k_w   = (const float*)d_in[10 + sh];
    const float* v_w   = (const float*)d_in[11 + sh];
    const float* cp_w  = (const float*)d_in[12 + sh];
    const float* cp_b  = (const float*)d_in[13 + sh];
    const float* fc1_w = (const float*)d_in[14 + sh];
    const float* fc1_b = (const float*)d_in[15 + sh];
    const float* fc2_w = (const float*)d_in[16 + sh];
    const float* fc2_b = (const float*)d_in[17 + sh];
    const float* ln1w = (const float*)d_in[18 + sh];
    const float* ln1b = (const float*)d_in[19 + sh];
    const float* ln2w = (const float*)d_in[20 + sh];
    const float* ln2b = (const float*)d_in[21 + sh];
    const float* ln3w = (const float*)d_in[22 + sh];
    const float* ln3b = (const float*)d_in[23 + sh];
    const float* lnyw = (const float*)d_in[24 + sh];
    const float* lnyb = (const float*)d_in[25 + sh];
    float* out = (float*)d_out;

    float *x, *h, *yn, *qkv, *q, *k, *v, *o, *big, *big2, *S;
    cudaGetSymbolAddress((void**)&x, g_x);
    cudaGetSymbolAddress((void**)&h, g_h);
    cudaGetSymbolAddress((void**)&yn, g_yn);
    cudaGetSymbolAddress((void**)&qkv, g_qkv);
    cudaGetSymbolAddress((void**)&q, g_q);
    cudaGetSymbolAddress((void**)&k, g_k);
    cudaGetSymbolAddress((void**)&v, g_v);
    cudaGetSymbolAddress((void**)&o, g_o);
    cudaGetSymbolAddress((void**)&big, g_big);
    cudaGetSymbolAddress((void**)&big2, g_big2);
    cudaGetSymbolAddress((void**)&S, g_S);

    // x = xs
    copy_kernel<<<(T * CC + 255) / 256, 256>>>(xs, x, T * CC);

    // ---- self attention ----
    layernorm_kernel<<<T, 256>>>(x, ln1w, ln1b, h);
    sgemm_nt<0><<<dim3(3 * CC / 128, T / 128), 256>>>(h, qkv_w, nullptr, nullptr, qkv, T, 3 * CC, CC);
    attn_scores_kernel<false><<<dim3(4, 4, PSELF), 256>>>(qkv, nullptr, nullptr, S);
    softmax_kernel<<<(PSELF * NN + 3) / 4, dim3(32, 4)>>>(S, PSELF * NN);
    attn_av_kernel<false><<<dim3(1, 4, PSELF), 256>>>(S, qkv, nullptr, o);
    sgemm_nt<2><<<dim3(CC / 128, T / 128), 256>>>(o, ap_w, ap_b, x, x, T, CC, CC);

    // ---- cross attention ----
    layernorm_kernel<<<T, 256>>>(x, ln2w, ln2b, h);
    layernorm_kernel<<<T, 256>>>(ys, lnyw, lnyb, yn);
    sgemm_nt<0><<<dim3(CC / 128, T / 128), 256>>>(h, q_w, nullptr, nullptr, q, T, CC, CC);
    sgemm_nt<0><<<dim3(CC / 128, T / 128), 256>>>(yn, k_w, nullptr, nullptr, k, T, CC, CC);
    sgemm_nt<0><<<dim3(CC / 128, T / 128), 256>>>(yn, v_w, nullptr, nullptr, v, T, CC, CC);
    attn_scores_kernel<true><<<dim3(4, 4, PCROSS), 256>>>(q, k, rel, S);
    softmax_kernel<<<(PCROSS * NN + 3) / 4, dim3(32, 4)>>>(S, PCROSS * NN);
    attn_av_kernel<true><<<dim3(1, 4, PCROSS), 256>>>(S, v, rel, big);
    sgemm_nt<1><<<dim3(CC / 128, TT / 128), 256>>>(big, cp_w, cp_b, nullptr, big2, TT, CC, CC);
    merge_kernel<<<(T * CC + 255) / 256, 256>>>(big2, x);

    // ---- MLP ----
    layernorm_kernel<<<T, 256>>>(x, ln3w, ln3b, h);
    sgemm_nt<3><<<dim3(HID / 128, T / 128), 256>>>(h, fc1_w, fc1_b, nullptr, big2, T, HID, CC);
    sgemm_nt<2><<<dim3(CC / 128, T / 128), 256>>>(big2, fc2_w, fc2_b, x, out, T, CC, HID);
}

// round 2
// speedup vs baseline: 2.0552x; 2.0552x over previous
#include <cuda_runtime.h>
#include <math.h>
#include <stdint.h>

// ---------------------------------------------------------------------------
// MultiviewDecoderBlock (Vx=8, Vy=8, B=4, N=196, C=768, H=12, DH=64, M=4)
// TF32 tensor-core GEMMs + fused flash attention. Graph-capturable.
// ---------------------------------------------------------------------------

constexpr int VX = 8, BB = 4, NN = 196, CC = 768, HH = 12, DHH = 64, MV = 4;
constexpr int HID = 4 * CC;            // 3072
constexpr int VB = VX * BB;            // 32
constexpr int T  = VB * NN;            // 6272 tokens (x)
constexpr int TT = VX * MV * BB * NN;  // 25088 tokens (cross out)
constexpr int PSELF  = VB * HH;            // 384
constexpr int PCROSS = VX * MV * BB * HH;  // 1536
constexpr float ATTN_SCALE = 0.125f;       // 64^-0.5

// -------------------------- device scratch ---------------------------------
__device__ float g_x  [T * CC];
__device__ float g_h  [T * CC];
__device__ float g_yn [T * CC];
__device__ float g_qkv[T * 3 * CC];
__device__ float g_q  [T * CC];
__device__ float g_k  [T * CC];
__device__ float g_v  [T * CC];
__device__ float g_o  [T * CC];
__device__ float g_big [TT * CC];  // cross-attn output (25088 x 768)
__device__ float g_big2[TT * CC];  // cross proj out; reused as MLP hidden

extern __shared__ __align__(16) unsigned char dyn_smem[];

// ----------------------------- utility -------------------------------------
__global__ void copy_kernel(const float* __restrict__ src, float* __restrict__ dst, int n) {
    int i = blockIdx.x * blockDim.x + threadIdx.x;
    if (i < n) dst[i] = src[i];
}

__global__ void layernorm_kernel(const float* __restrict__ in,
                                 const float* __restrict__ w,
                                 const float* __restrict__ b,
                                 float* __restrict__ out) {
    int row = blockIdx.x;
    const float* xr = in + (size_t)row * CC;
    float* orow = out + (size_t)row * CC;
    int tid = threadIdx.x;
    float v0 = xr[tid], v1 = xr[tid + 256], v2 = xr[tid + 512];
    float s  = v0 + v1 + v2;
    float sq = v0 * v0 + v1 * v1 + v2 * v2;
    #pragma unroll
    for (int off = 16; off; off >>= 1) {
        s  += __shfl_xor_sync(0xffffffffu, s, off);
        sq += __shfl_xor_sync(0xffffffffu, sq, off);
    }
    __shared__ float red[2][8];
    int warp = tid >> 5, lane = tid & 31;
    if (lane == 0) { red[0][warp] = s; red[1][warp] = sq; }
    __syncthreads();
    float ts = 0.f, tsq = 0.f;
    #pragma unroll
    for (int i = 0; i < 8; i++) { ts += red[0][i]; tsq += red[1][i]; }
    float mu = ts * (1.0f / CC);
    float var = tsq * (1.0f / CC) - mu * mu;
    float rstd = rsqrtf(var + 1e-5f);
    orow[tid]       = (v0 - mu) * rstd * w[tid]       + b[tid];
    orow[tid + 256] = (v1 - mu) * rstd * w[tid + 256] + b[tid + 256];
    orow[tid + 512] = (v2 - mu) * rstd * w[tid + 512] + b[tid + 512];
}

// ------------------- max-merge over M and residual add ----------------------
__global__ void merge_kernel(const float* __restrict__ proj, float* __restrict__ x) {
    int idx = blockIdx.x * blockDim.x + threadIdx.x;
    if (idx >= T * CC) return;
    int c = idx % CC;
    int n = (idx / CC) % NN;
    int b = (idx / (CC * NN)) % BB;
    int v = idx / (CC * NN * BB);
    size_t base = ((((size_t)v * MV) * BB + b) * NN + n) * CC + c;
    size_t ms = (size_t)BB * NN * CC;
    float mx = proj[base];
    #pragma unroll
    for (int m = 1; m < MV; m++) mx = fmaxf(mx, proj[base + (size_t)m * ms]);
    x[idx] += mx;
}

// ----------------------------- tf32 helpers ---------------------------------
__device__ __forceinline__ unsigned f2tf(float f) {
    unsigned u;
    asm("cvt.rna.tf32.f32 %0, %1;" : "=r"(u) : "f"(f));
    return u;
}

__device__ __forceinline__ void mma8(float* c, const unsigned* a, const unsigned* b) {
    asm volatile(
        "mma.sync.aligned.m16n8k8.row.col.f32.tf32.tf32.f32 "
        "{%0,%1,%2,%3},{%4,%5,%6,%7},{%8,%9},{%0,%1,%2,%3};\n"
        : "+f"(c[0]), "+f"(c[1]), "+f"(c[2]), "+f"(c[3])
        : "r"(a[0]), "r"(a[1]), "r"(a[2]), "r"(a[3]), "r"(b[0]), "r"(b[1]));
}

// --------------------- TF32 tensor GEMM: C = A @ B^T ------------------------
// A: (M,K) row-major, B: (N,K) row-major. M%128==0, N%128==0, K%32==0.
// 128x128x32 tile, 256 threads, warp tile 64x32.
// smem layout: [row][32 k], XOR swizzle on 4-float groups: g = (k>>2) ^ (row&7).
// EPI: 0=store, 1=+bias, 2=+bias+residual, 3=+bias+gelu(exact)
constexpr int GEMM_SMEM = 2 * 128 * 32 * 4 * 2;  // 65536 bytes

template<int EPI>
__global__ void __launch_bounds__(256) gemm_tf32(
    const float* __restrict__ A, const float* __restrict__ Bw,
    const float* __restrict__ bias, const float* __restrict__ res,
    float* __restrict__ C, int Mdim, int Ndim, int Kdim)
{
    unsigned* As = (unsigned*)dyn_smem;             // [2][128][32]
    unsigned* Bs = As + 2 * 128 * 32;

    const int tid = threadIdx.x;
    const int lane = tid & 31, warp = tid >> 5;
    const int wm = (warp >> 2) * 64;   // 0 / 64
    const int wn = (warp & 3) * 32;    // 0..96
    const int bm = blockIdx.y * 128, bn = blockIdx.x * 128;
    const int lr = tid >> 3;           // 0..31
    const int lk = (tid & 7) * 4;      // 0..28
    const float* Ag = A  + (size_t)(bm + lr) * Kdim + lk;
    const float* Bg = Bw + (size_t)(bn + lr) * Kdim + lk;

    float acc[4][4][4];
    #pragma unroll
    for (int i = 0; i < 4; i++)
        #pragma unroll
        for (int j = 0; j < 4; j++)
            #pragma unroll
            for (int t = 0; t < 4; t++) acc[i][j][t] = 0.f;

    float4 pa[4], pb[4];
    #pragma unroll
    for (int i = 0; i < 4; i++) {
        pa[i] = *(const float4*)(Ag + (size_t)(32 * i) * Kdim);
        pb[i] = *(const float4*)(Bg + (size_t)(32 * i) * Kdim);
    }
    // store chunk 0
    {
        #pragma unroll
        for (int i = 0; i < 4; i++) {
            int row = lr + 32 * i;
            int g = (lk >> 2) ^ (row & 7);
            uint4 av, bv;
            av.x = f2tf(pa[i].x); av.y = f2tf(pa[i].y); av.z = f2tf(pa[i].z); av.w = f2tf(pa[i].w);
            bv.x = f2tf(pb[i].x); bv.y = f2tf(pb[i].y); bv.z = f2tf(pb[i].z); bv.w = f2tf(pb[i].w);
            *(uint4*)(As + row * 32 + g * 4) = av;
            *(uint4*)(Bs + row * 32 + g * 4) = bv;
        }
    }
    __syncthreads();

    const int r = lane >> 2, kq = lane & 3;
    const int nk = Kdim >> 5;
    for (int kt = 0; kt < nk; kt++) {
        const int buf = kt & 1;
        if (kt + 1 < nk) {
            const float* Ag2 = Ag + (kt + 1) * 32;
            const float* Bg2 = Bg + (kt + 1) * 32;
            #pragma unroll
            for (int i = 0; i < 4; i++) {
                pa[i] = *(const float4*)(Ag2 + (size_t)(32 * i) * Kdim);
                pb[i] = *(const float4*)(Bg2 + (size_t)(32 * i) * Kdim);
            }
        }
        // compute
        {
            const unsigned* Ab = As + buf * 4096;
            const unsigned* Bb = Bs + buf * 4096;
            #pragma unroll
            for (int ks = 0; ks < 4; ks++) {
                const int g0 = (((2 * ks)     ^ r) << 2) + kq;
                const int g1 = (((2 * ks + 1) ^ r) << 2) + kq;
                unsigned a[4][4], b[4][2];
                #pragma unroll
                for (int mf = 0; mf < 4; mf++) {
                    const unsigned* p = Ab + (wm + mf * 16 + r) * 32;
                    a[mf][0] = p[g0];
                    a[mf][1] = p[8 * 32 + g0];
                    a[mf][2] = p[g1];
                    a[mf][3] = p[8 * 32 + g1];
                }
                #pragma unroll
                for (int nf = 0; nf < 4; nf++) {
                    const unsigned* p = Bb + (wn + nf * 8 + r) * 32;
                    b[nf][0] = p[g0];
                    b[nf][1] = p[g1];
                }
                #pragma unroll
                for (int mf = 0; mf < 4; mf++)
                    #pragma unroll
                    for (int nf = 0; nf < 4; nf++)
                        mma8(acc[mf][nf], a[mf], b[nf]);
            }
        }
        if (kt + 1 < nk) {
            unsigned* Ad = As + (buf ^ 1) * 4096;
            unsigned* Bd = Bs + (buf ^ 1) * 4096;
            #pragma unroll
            for (int i = 0; i < 4; i++) {
                int row = lr + 32 * i;
                int g = (lk >> 2) ^ (row & 7);
                uint4 av, bv;
                av.x = f2tf(pa[i].x); av.y = f2tf(pa[i].y); av.z = f2tf(pa[i].z); av.w = f2tf(pa[i].w);
                bv.x = f2tf(pb[i].x); bv.y = f2tf(pb[i].y); bv.z = f2tf(pb[i].z); bv.w = f2tf(pb[i].w);
                *(uint4*)(Ad + row * 32 + g * 4) = av;
                *(uint4*)(Bd + row * 32 + g * 4) = bv;
            }
        }
        __syncthreads();
    }

    // epilogue
    #pragma unroll
    for (int mf = 0; mf < 4; mf++) {
        #pragma unroll
        for (int nf = 0; nf < 4; nf++) {
            const int col = bn + wn + nf * 8 + (lane & 3) * 2;
            float bb0 = 0.f, bb1 = 0.f;
            if (EPI >= 1) { bb0 = bias[col]; bb1 = bias[col + 1]; }
            #pragma unroll
            for (int hh = 0; hh < 2; hh++) {
                const size_t row = (size_t)(bm + wm + mf * 16 + (lane >> 2) + hh * 8);
                float v0 = acc[mf][nf][hh * 2 + 0] + bb0;
                float v1 = acc[mf][nf][hh * 2 + 1] + bb1;
                if (EPI == 2) {
                    v0 += res[row * Ndim + col];
                    v1 += res[row * Ndim + col + 1];
                }
                if (EPI == 3) {
                    v0 = 0.5f * v0 * (1.0f + erff(v0 * 0.70710678118654752f));
                    v1 = 0.5f * v1 * (1.0f + erff(v1 * 0.70710678118654752f));
                }
                *(float2*)(C + row * Ndim + col) = make_float2(v0, v1);
            }
        }
    }
}

// ------------------- fused flash attention (fp32) ---------------------------
// One block: one head-problem p, 64 query rows. 256 threads = 16x16,
// 4x4 per-thread tiles. Online softmax over 4 key chunks of 64.
// smem: Qs [64k][68m], Ks [64k][68n], Ps [64n][68m], Vs [64n][68dh]
constexpr int ATTN_SMEM = 4 * 64 * 68 * 4;  // 69632 bytes

template<bool CROSS>
__global__ void __launch_bounds__(256) attn_fused(
    const float* __restrict__ Qsrc, const float* __restrict__ Ksrc,
    const float* __restrict__ Vsrc, const int* __restrict__ rel,
    float* __restrict__ Out)
{
    float* Qs = (float*)dyn_smem;
    float* Ks = Qs + 64 * 68;
    float* Ps = Ks + 64 * 68;
    float* Vs = Ps + 64 * 68;

    const int p = blockIdx.y;
    const int m0 = blockIdx.x * 64;
    const int tid = threadIdx.x;
    const int ty = tid >> 4, tx = tid & 15;

    const float *qp, *kp, *vp;
    float* op;
    int qrs, kvs;
    if (!CROSS) {
        int vb = p / HH, h2 = p % HH;
        const float* base = Qsrc + (size_t)vb * NN * 3 * CC;
        qp = base + h2 * DHH;
        kp = base + CC + h2 * DHH;
        vp = base + 2 * CC + h2 * DHH;
        qrs = 3 * CC; kvs = 3 * CC;
        op = Out + (size_t)vb * NN * CC + h2 * DHH;
    } else {
        int h2 = p % HH; int rr = p / HH;
        int b = rr % BB; int r2 = rr / BB;
        int mvi = r2 % MV; int v = r2 / MV;
        int vy = rel[v * MV + mvi];
        qp = Qsrc + ((size_t)(v * BB + b) * NN) * CC + h2 * DHH; qrs = CC;
        kp = Ksrc + ((size_t)(vy * BB + b) * NN) * CC + h2 * DHH;
        vp = Vsrc + ((size_t)(vy * BB + b) * NN) * CC + h2 * DHH; kvs = CC;
        op = Out + (size_t)rr * NN * CC + h2 * DHH;
    }

    // load Q tile transposed -> Qs[k][m]
    #pragma unroll
    for (int it = 0; it < 4; it++) {
        int idx = tid + 256 * it;
        int mm = idx >> 4, k4 = (idx & 15) * 4;
        float4 qv = make_float4(0.f, 0.f, 0.f, 0.f);
        if (m0 + mm < NN) qv = *(const float4*)(qp + (size_t)(m0 + mm) * qrs + k4);
        Qs[(k4 + 0) * 68 + mm] = qv.x;
        Qs[(k4 + 1) * 68 + mm] = qv.y;
        Qs[(k4 + 2) * 68 + mm] = qv.z;
        Qs[(k4 + 3) * 68 + mm] = qv.w;
    }

    float rmax[4], rsum[4], oacc[4][4];
    #pragma unroll
    for (int i = 0; i < 4; i++) {
        rmax[i] = -1e30f; rsum[i] = 0.f;
        #pragma unroll
        for (int j = 0; j < 4; j++) oacc[i][j] = 0.f;
    }
    __syncthreads();

    #pragma unroll 1
    for (int c = 0; c < 4; c++) {
        // load K chunk (transposed) and V chunk (natural)
        #pragma unroll
        for (int it = 0; it < 4; it++) {
            int idx = tid + 256 * it;
            int row = idx >> 4, k4 = (idx & 15) * 4;
            int n = c * 64 + row;
            float4 kv = make_float4(0.f, 0.f, 0.f, 0.f);
            float4 vv = make_float4(0.f, 0.f, 0.f, 0.f);
            if (n < NN) {
                kv = *(const float4*)(kp + (size_t)n * kvs + k4);
                vv = *(const float4*)(vp + (size_t)n * kvs + k4);
            }
            Ks[(k4 + 0) * 68 + row] = kv.x;
            Ks[(k4 + 1) * 68 + row] = kv.y;
            Ks[(k4 + 2) * 68 + row] = kv.z;
            Ks[(k4 + 3) * 68 + row] = kv.w;
            *(float4*)&Vs[row * 68 + k4] = vv;
        }
        __syncthreads();

        // scores 64x64 chunk
        float s[4][4];
        #pragma unroll
        for (int i = 0; i < 4; i++)
            #pragma unroll
            for (int j = 0; j < 4; j++) s[i][j] = 0.f;
        #pragma unroll 8
        for (int k = 0; k < 64; k++) {
            float4 a = *(const float4*)&Qs[k * 68 + ty * 4];
            float4 b = *(const float4*)&Ks[k * 68 + tx * 4];
            float ar[4] = {a.x, a.y, a.z, a.w};
            float br[4] = {b.x, b.y, b.z, b.w};
            #pragma unroll
            for (int i = 0; i < 4; i++)
                #pragma unroll
                for (int j = 0; j < 4; j++)
                    s[i][j] += ar[i] * br[j];
        }
        // scale + mask invalid keys
        #pragma unroll
        for (int i = 0; i < 4; i++)
            #pragma unroll
            for (int j = 0; j < 4; j++) {
                s[i][j] *= ATTN_SCALE;
                if (c * 64 + tx * 4 + j >= NN) s[i][j] = -1e30f;
            }
        // online softmax update
        #pragma unroll
        for (int i = 0; i < 4; i++) {
            float cm = fmaxf(fmaxf(s[i][0], s[i][1]), fmaxf(s[i][2], s[i][3]));
            #pragma unroll
            for (int off = 8; off; off >>= 1)
                cm = fmaxf(cm, __shfl_xor_sync(0xffffffffu, cm, off));
            float nm = fmaxf(rmax[i], cm);
            float alpha = __expf(rmax[i] - nm);
            rmax[i] = nm;
            float ls = 0.f;
            #pragma unroll
            for (int j = 0; j < 4; j++) {
                float e = __expf(s[i][j] - nm);
                s[i][j] = e; ls += e;
            }
            #pragma unroll
            for (int off = 8; off; off >>= 1)
                ls += __shfl_xor_sync(0xffffffffu, ls, off);
            rsum[i] = rsum[i] * alpha + ls;
            #pragma unroll
            for (int j = 0; j < 4; j++) oacc[i][j] *= alpha;
        }
        // store P transposed: Ps[n][m]
        #pragma unroll
        for (int j = 0; j < 4; j++)
            #pragma unroll
            for (int i = 0; i < 4; i++)
                Ps[(tx * 4 + j) * 68 + ty * 4 + i] = s[i][j];
        __syncthreads();

        // O += P @ V
        #pragma unroll 8
        for (int n = 0; n < 64; n++) {
            float4 a = *(const float4*)&Ps[n * 68 + ty * 4];
            float4 b = *(const float4*)&Vs[n * 68 + tx * 4];
            float ar[4] = {a.x, a.y, a.z, a.w};
            float br[4] = {b.x, b.y, b.z, b.w};
            #pragma unroll
            for (int i = 0; i < 4; i++)
                #pragma unroll
                for (int j = 0; j < 4; j++)
                    oacc[i][j] += ar[i] * br[j];
        }
        __syncthreads();
    }

    // write output
    #pragma unroll
    for (int i = 0; i < 4; i++) {
        int m = m0 + ty * 4 + i;
        if (m < NN) {
            float inv = 1.0f / rsum[i];
            float4 o = make_float4(oacc[i][0] * inv, oacc[i][1] * inv,
                                   oacc[i][2] * inv, oacc[i][3] * inv);
            *(float4*)(op + (size_t)m * CC + tx * 4) = o;
        }
    }
}

// ------------------------------- launch -------------------------------------
extern "C" void kernel_launch(void* const* d_in, const int* in_sizes, int n_in,
                              void* d_out, int out_size) {
    int sh = (in_sizes[5] == 1) ? 0 : -1;

    const float* xs  = (const float*)d_in[0];
    const float* ys  = (const float*)d_in[1];
    const int* rel   = (const int*)d_in[4];
    const float* qkv_w = (const float*)d_in[6 + sh];
    const float* ap_w  = (const float*)d_in[7 + sh];
    const float* ap_b  = (const float*)d_in[8 + sh];
    const float* q_w   = (const float*)d_in[9 + sh];
    const float* k_w   = (const float*)d_in[10 + sh];
    const float* v_w   = (const float*)d_in[11 + sh];
    const float* cp_w  = (const float*)d_in[12 + sh];
    const float* cp_b  = (const float*)d_in[13 + sh];
    const float* fc1_w = (const float*)d_in[14 + sh];
    const float* fc1_b = (const float*)d_in[15 + sh];
    const float* fc2_w = (const float*)d_in[16 + sh];
    const float* fc2_b = (const float*)d_in[17 + sh];
    const float* ln1w = (const float*)d_in[18 + sh];
    const float* ln1b = (const float*)d_in[19 + sh];
    const float* ln2w = (const float*)d_in[20 + sh];
    const float* ln2b = (const float*)d_in[21 + sh];
    const float* ln3w = (const float*)d_in[22 + sh];
    const float* ln3b = (const float*)d_in[23 + sh];
    const float* lnyw = (const float*)d_in[24 + sh];
    const float* lnyb = (const float*)d_in[25 + sh];
    float* out = (float*)d_out;

    float *x, *h, *yn, *qkv, *q, *k, *v, *o, *big, *big2;
    cudaGetSymbolAddress((void**)&x, g_x);
    cudaGetSymbolAddress((void**)&h, g_h);
    cudaGetSymbolAddress((void**)&yn, g_yn);
    cudaGetSymbolAddress((void**)&qkv, g_qkv);
    cudaGetSymbolAddress((void**)&q, g_q);
    cudaGetSymbolAddress((void**)&k, g_k);
    cudaGetSymbolAddress((void**)&v, g_v);
    cudaGetSymbolAddress((void**)&o, g_o);
    cudaGetSymbolAddress((void**)&big, g_big);
    cudaGetSymbolAddress((void**)&big2, g_big2);

    // opt-in large dynamic smem (idempotent)
    cudaFuncSetAttribute(gemm_tf32<0>, cudaFuncAttributeMaxDynamicSharedMemorySize, GEMM_SMEM);
    cudaFuncSetAttribute(gemm_tf32<1>, cudaFuncAttributeMaxDynamicSharedMemorySize, GEMM_SMEM);
    cudaFuncSetAttribute(gemm_tf32<2>, cudaFuncAttributeMaxDynamicSharedMemorySize, GEMM_SMEM);
    cudaFuncSetAttribute(gemm_tf32<3>, cudaFuncAttributeMaxDynamicSharedMemorySize, GEMM_SMEM);
    cudaFuncSetAttribute(attn_fused<false>, cudaFuncAttributeMaxDynamicSharedMemorySize, ATTN_SMEM);
    cudaFuncSetAttribute(attn_fused<true>,  cudaFuncAttributeMaxDynamicSharedMemorySize, ATTN_SMEM);

    copy_kernel<<<(T * CC + 255) / 256, 256>>>(xs, x, T * CC);

    // ---- self attention ----
    layernorm_kernel<<<T, 256>>>(x, ln1w, ln1b, h);
    gemm_tf32<0><<<dim3(3 * CC / 128, T / 128), 256, GEMM_SMEM>>>(h, qkv_w, nullptr, nullptr, qkv, T, 3 * CC, CC);
    attn_fused<false><<<dim3(4, PSELF), 256, ATTN_SMEM>>>(qkv, qkv, qkv, nullptr, o);
    gemm_tf32<2><<<dim3(CC / 128, T / 128), 256, GEMM_SMEM>>>(o, ap_w, ap_b, x, x, T, CC, CC);

    // ---- cross attention ----
    layernorm_kernel<<<T, 256>>>(x, ln2w, ln2b, h);
    layernorm_kernel<<<T, 256>>>(ys, lnyw, lnyb, yn);
    gemm_tf32<0><<<dim3(CC / 128, T / 128), 256, GEMM_SMEM>>>(h, q_w, nullptr, nullptr, q, T, CC, CC);
    gemm_tf32<0><<<dim3(CC / 128, T / 128), 256, GEMM_SMEM>>>(yn, k_w, nullptr, nullptr, k, T, CC, CC);
    gemm_tf32<0><<<dim3(CC / 128, T / 128), 256, GEMM_SMEM>>>(yn, v_w, nullptr, nullptr, v, T, CC, CC);
    attn_fused<true><<<dim3(4, PCROSS), 256, ATTN_SMEM>>>(q, k, v, rel, big);
    gemm_tf32<1><<<dim3(CC / 128, TT / 128), 256, GEMM_SMEM>>>(big, cp_w, cp_b, nullptr, big2, TT, CC, CC);
    merge_kernel<<<(T * CC + 255) / 256, 256>>>(big2, x);

    // ---- MLP ----
    layernorm_kernel<<<T, 256>>>(x, ln3w, ln3b, h);
    gemm_tf32<3><<<dim3(HID / 128, T / 128), 256, GEMM_SMEM>>>(h, fc1_w, fc1_b, nullptr, big2, T, HID, CC);
    gemm_tf32<2><<<dim3(CC / 128, T / 128), 256, GEMM_SMEM>>>(big2, fc2_w, fc2_b, x, out, T, CC, HID);
}

// round 3
// speedup vs baseline: 2.7512x; 1.3386x over previous
#include <cuda_runtime.h>
#include <math.h>
#include <stdint.h>

// ---------------------------------------------------------------------------
// MultiviewDecoderBlock (Vx=8, Vy=8, B=4, N=196, C=768, H=12, DH=64, M=4)
// TF32 tensor-core GEMMs + TF32 tensor-core attention. Graph-capturable.
// ---------------------------------------------------------------------------

constexpr int VX = 8, BB = 4, NN = 196, CC = 768, HH = 12, DHH = 64, MV = 4;
constexpr int HID = 4 * CC;            // 3072
constexpr int VB = VX * BB;            // 32
constexpr int T  = VB * NN;            // 6272 tokens (x)
constexpr int TT = VX * MV * BB * NN;  // 25088 tokens (cross out)
constexpr int PSELF  = VB * HH;            // 384
constexpr int PCROSS = VX * MV * BB * HH;  // 1536
constexpr float ATTN_SCALE = 0.125f;       // 64^-0.5

// -------------------------- device scratch ---------------------------------
__device__ float g_x  [T * CC];
__device__ float g_h  [T * CC];
__device__ float g_yn [T * CC];
__device__ float g_qkv[T * 3 * CC];
__device__ float g_q  [T * CC];
__device__ float g_k  [T * CC];
__device__ float g_v  [T * CC];
__device__ float g_o  [T * CC];
__device__ float g_big [TT * CC];
__device__ float g_big2[TT * CC];

extern __shared__ __align__(16) unsigned char dyn_smem[];

// ----------------------------- utility -------------------------------------
__global__ void copy_kernel(const float* __restrict__ src, float* __restrict__ dst, int n) {
    int i = blockIdx.x * blockDim.x + threadIdx.x;
    if (i < n) dst[i] = src[i];
}

__global__ void layernorm_kernel(const float* __restrict__ in,
                                 const float* __restrict__ w,
                                 const float* __restrict__ b,
                                 float* __restrict__ out) {
    int row = blockIdx.x;
    const float* xr = in + (size_t)row * CC;
    float* orow = out + (size_t)row * CC;
    int tid = threadIdx.x;
    float v0 = xr[tid], v1 = xr[tid + 256], v2 = xr[tid + 512];
    float s  = v0 + v1 + v2;
    float sq = v0 * v0 + v1 * v1 + v2 * v2;
    #pragma unroll
    for (int off = 16; off; off >>= 1) {
        s  += __shfl_xor_sync(0xffffffffu, s, off);
        sq += __shfl_xor_sync(0xffffffffu, sq, off);
    }
    __shared__ float red[2][8];
    int warp = tid >> 5, lane = tid & 31;
    if (lane == 0) { red[0][warp] = s; red[1][warp] = sq; }
    __syncthreads();
    float ts = 0.f, tsq = 0.f;
    #pragma unroll
    for (int i = 0; i < 8; i++) { ts += red[0][i]; tsq += red[1][i]; }
    float mu = ts * (1.0f / CC);
    float var = tsq * (1.0f / CC) - mu * mu;
    float rstd = rsqrtf(var + 1e-5f);
    orow[tid]       = (v0 - mu) * rstd * w[tid]       + b[tid];
    orow[tid + 256] = (v1 - mu) * rstd * w[tid + 256] + b[tid + 256];
    orow[tid + 512] = (v2 - mu) * rstd * w[tid + 512] + b[tid + 512];
}

__global__ void merge_kernel(const float* __restrict__ proj, float* __restrict__ x) {
    int idx = blockIdx.x * blockDim.x + threadIdx.x;
    if (idx >= T * CC) return;
    int c = idx % CC;
    int n = (idx / CC) % NN;
    int b = (idx / (CC * NN)) % BB;
    int v = idx / (CC * NN * BB);
    size_t base = ((((size_t)v * MV) * BB + b) * NN + n) * CC + c;
    size_t ms = (size_t)BB * NN * CC;
    float mx = proj[base];
    #pragma unroll
    for (int m = 1; m < MV; m++) mx = fmaxf(mx, proj[base + (size_t)m * ms]);
    x[idx] += mx;
}

// ----------------------------- tf32 helpers ---------------------------------
__device__ __forceinline__ unsigned f2tf(float f) {
    unsigned u;
    asm("cvt.rna.tf32.f32 %0, %1;" : "=r"(u) : "f"(f));
    return u;
}

__device__ __forceinline__ void mma8(float* c, const unsigned* a, const unsigned* b) {
    asm volatile(
        "mma.sync.aligned.m16n8k8.row.col.f32.tf32.tf32.f32 "
        "{%0,%1,%2,%3},{%4,%5,%6,%7},{%8,%9},{%0,%1,%2,%3};\n"
        : "+f"(c[0]), "+f"(c[1]), "+f"(c[2]), "+f"(c[3])
        : "r"(a[0]), "r"(a[1]), "r"(a[2]), "r"(a[3]), "r"(b[0]), "r"(b[1]));
}

// --------------------- TF32 tensor GEMM: C = A @ B^T ------------------------
constexpr int GEMM_SMEM = 2 * 128 * 32 * 4 * 2;  // 65536 bytes

template<int EPI>
__global__ void __launch_bounds__(256) gemm_tf32(
    const float* __restrict__ A, const float* __restrict__ Bw,
    const float* __restrict__ bias, const float* __restrict__ res,
    float* __restrict__ C, int Mdim, int Ndim, int Kdim)
{
    unsigned* As = (unsigned*)dyn_smem;             // [2][128][32]
    unsigned* Bs = As + 2 * 128 * 32;

    const int tid = threadIdx.x;
    const int lane = tid & 31, warp = tid >> 5;
    const int wm = (warp >> 2) * 64;
    const int wn = (warp & 3) * 32;
    const int bm = blockIdx.y * 128, bn = blockIdx.x * 128;
    const int lr = tid >> 3;
    const int lk = (tid & 7) * 4;
    const float* Ag = A  + (size_t)(bm + lr) * Kdim + lk;
    const float* Bg = Bw + (size_t)(bn + lr) * Kdim + lk;

    float acc[4][4][4];
    #pragma unroll
    for (int i = 0; i < 4; i++)
        #pragma unroll
        for (int j = 0; j < 4; j++)
            #pragma unroll
            for (int t = 0; t < 4; t++) acc[i][j][t] = 0.f;

    float4 pa[4], pb[4];
    #pragma unroll
    for (int i = 0; i < 4; i++) {
        pa[i] = *(const float4*)(Ag + (size_t)(32 * i) * Kdim);
        pb[i] = *(const float4*)(Bg + (size_t)(32 * i) * Kdim);
    }
    {
        #pragma unroll
        for (int i = 0; i < 4; i++) {
            int row = lr + 32 * i;
            int g = (lk >> 2) ^ (row & 7);
            uint4 av, bv;
            av.x = f2tf(pa[i].x); av.y = f2tf(pa[i].y); av.z = f2tf(pa[i].z); av.w = f2tf(pa[i].w);
            bv.x = f2tf(pb[i].x); bv.y = f2tf(pb[i].y); bv.z = f2tf(pb[i].z); bv.w = f2tf(pb[i].w);
            *(uint4*)(As + row * 32 + g * 4) = av;
            *(uint4*)(Bs + row * 32 + g * 4) = bv;
        }
    }
    __syncthreads();

    const int r = lane >> 2, kq = lane & 3;
    const int nk = Kdim >> 5;
    for (int kt = 0; kt < nk; kt++) {
        const int buf = kt & 1;
        if (kt + 1 < nk) {
            const float* Ag2 = Ag + (kt + 1) * 32;
            const float* Bg2 = Bg + (kt + 1) * 32;
            #pragma unroll
            for (int i = 0; i < 4; i++) {
                pa[i] = *(const float4*)(Ag2 + (size_t)(32 * i) * Kdim);
                pb[i] = *(const float4*)(Bg2 + (size_t)(32 * i) * Kdim);
            }
        }
        {
            const unsigned* Ab = As + buf * 4096;
            const unsigned* Bb = Bs + buf * 4096;
            #pragma unroll
            for (int ks = 0; ks < 4; ks++) {
                const int g0 = (((2 * ks)     ^ r) << 2) + kq;
                const int g1 = (((2 * ks + 1) ^ r) << 2) + kq;
                unsigned a[4][4], b[4][2];
                #pragma unroll
                for (int mf = 0; mf < 4; mf++) {
                    const unsigned* p = Ab + (wm + mf * 16 + r) * 32;
                    a[mf][0] = p[g0];
                    a[mf][1] = p[8 * 32 + g0];
                    a[mf][2] = p[g1];
                    a[mf][3] = p[8 * 32 + g1];
                }
                #pragma unroll
                for (int nf = 0; nf < 4; nf++) {
                    const unsigned* p = Bb + (wn + nf * 8 + r) * 32;
                    b[nf][0] = p[g0];
                    b[nf][1] = p[g1];
                }
                #pragma unroll
                for (int mf = 0; mf < 4; mf++)
                    #pragma unroll
                    for (int nf = 0; nf < 4; nf++)
                        mma8(acc[mf][nf], a[mf], b[nf]);
            }
        }
        if (kt + 1 < nk) {
            unsigned* Ad = As + (buf ^ 1) * 4096;
            unsigned* Bd = Bs + (buf ^ 1) * 4096;
            #pragma unroll
            for (int i = 0; i < 4; i++) {
                int row = lr + 32 * i;
                int g = (lk >> 2) ^ (row & 7);
                uint4 av, bv;
                av.x = f2tf(pa[i].x); av.y = f2tf(pa[i].y); av.z = f2tf(pa[i].z); av.w = f2tf(pa[i].w);
                bv.x = f2tf(pb[i].x); bv.y = f2tf(pb[i].y); bv.z = f2tf(pb[i].z); bv.w = f2tf(pb[i].w);
                *(uint4*)(Ad + row * 32 + g * 4) = av;
                *(uint4*)(Bd + row * 32 + g * 4) = bv;
            }
        }
        __syncthreads();
    }

    #pragma unroll
    for (int mf = 0; mf < 4; mf++) {
        #pragma unroll
        for (int nf = 0; nf < 4; nf++) {
            const int col = bn + wn + nf * 8 + (lane & 3) * 2;
            float bb0 = 0.f, bb1 = 0.f;
            if (EPI >= 1) { bb0 = bias[col]; bb1 = bias[col + 1]; }
            #pragma unroll
            for (int hh = 0; hh < 2; hh++) {
                const size_t row = (size_t)(bm + wm + mf * 16 + (lane >> 2) + hh * 8);
                float v0 = acc[mf][nf][hh * 2 + 0] + bb0;
                float v1 = acc[mf][nf][hh * 2 + 1] + bb1;
                if (EPI == 2) {
                    v0 += res[row * Ndim + col];
                    v1 += res[row * Ndim + col + 1];
                }
                if (EPI == 3) {
                    v0 = 0.5f * v0 * (1.0f + erff(v0 * 0.70710678118654752f));
                    v1 = 0.5f * v1 * (1.0f + erff(v1 * 0.70710678118654752f));
                }
                *(float2*)(C + row * Ndim + col) = make_float2(v0, v1);
            }
        }
    }
}

// ------------------- TF32 mma attention ---------------------------------
// One block: one head-problem p, 64 query rows. 256 threads = 8 warps:
// warp = wn*4 + wm; wm selects 16 query rows, wn selects 104-key half.
// Keys padded to 208 (26 tiles of 8). Scores fully materialized in regs.
constexpr int KP   = 208;   // padded key count
constexpr int NTJ  = 13;    // score n-tiles per warp (104 keys)
constexpr int KST  = 68;    // Q/K/V smem stride (floats)
constexpr int PST  = 212;   // P smem stride (floats)
constexpr int OFF_Q = 0;                       // 64*68   = 4352
constexpr int OFF_K = 64 * KST;                // 4352
constexpr int OFF_V = OFF_K + KP * KST;        // 18496
constexpr int OFF_RED = OFF_V + KP * KST;      // 32640 : redmax[2][64], redsum[2][64]
constexpr int ATTN_SMEM = (OFF_RED + 256) * 4; // 131584 bytes

template<bool CROSS>
__global__ void __launch_bounds__(256) attn_mma(
    const float* __restrict__ Qsrc, const float* __restrict__ Ksrc,
    const float* __restrict__ Vsrc, const int* __restrict__ rel,
    float* __restrict__ Out)
{
    float* smem = (float*)dyn_smem;
    float* Qs = smem + OFF_Q;
    float* Ks = smem + OFF_K;
    float* Vs = smem + OFF_V;
    float* Ps = smem;           // overlaps Q+K after scores are in regs
    float* redmax = smem + OFF_RED;        // [2][64]
    float* redsum = smem + OFF_RED + 128;  // [2][64]

    const int p = blockIdx.y;
    const int m0 = blockIdx.x * 64;
    const int tid = threadIdx.x;
    const int lane = tid & 31, warp = tid >> 5;
    const int wm = warp & 3, wn = warp >> 2;
    const int r = lane >> 2, q = lane & 3;

    const float *qp, *kp, *vp;
    float* op;
    int qrs, kvs;
    if (!CROSS) {
        int vb = p / HH, h2 = p % HH;
        const float* base = Qsrc + (size_t)vb * NN * 3 * CC;
        qp = base + h2 * DHH;
        kp = base + CC + h2 * DHH;
        vp = base + 2 * CC + h2 * DHH;
        qrs = 3 * CC; kvs = 3 * CC;
        op = Out + (size_t)vb * NN * CC + h2 * DHH;
    } else {
        int h2 = p % HH; int rr = p / HH;
        int b = rr % BB; int r2 = rr / BB;
        int mvi = r2 % MV; int v = r2 / MV;
        int vy = rel[v * MV + mvi];
        qp = Qsrc + ((size_t)(v * BB + b) * NN) * CC + h2 * DHH; qrs = CC;
        kp = Ksrc + ((size_t)(vy * BB + b) * NN) * CC + h2 * DHH;
        vp = Vsrc + ((size_t)(vy * BB + b) * NN) * CC + h2 * DHH; kvs = CC;
        op = Out + (size_t)rr * NN * CC + h2 * DHH;
    }

    // ---- load Q (64 x 64), tf32-converted ----
    #pragma unroll
    for (int it = 0; it < 4; it++) {
        int idx = tid + 256 * it;
        int row = idx >> 4, c4 = (idx & 15) * 4;
        float4 qv = make_float4(0.f, 0.f, 0.f, 0.f);
        if (m0 + row < NN) qv = *(const float4*)(qp + (size_t)(m0 + row) * qrs + c4);
        unsigned* d = (unsigned*)&Qs[row * KST + c4];
        d[0] = f2tf(qv.x); d[1] = f2tf(qv.y); d[2] = f2tf(qv.z); d[3] = f2tf(qv.w);
    }
    // ---- load K, V (208 x 64), zero-padded rows >= 196 ----
    #pragma unroll
    for (int it = 0; it < 13; it++) {
        int idx = tid + 256 * it;
        int row = idx >> 4, c4 = (idx & 15) * 4;
        float4 kv = make_float4(0.f, 0.f, 0.f, 0.f);
        float4 vv = make_float4(0.f, 0.f, 0.f, 0.f);
        if (row < NN) {
            kv = *(const float4*)(kp + (size_t)row * kvs + c4);
            vv = *(const float4*)(vp + (size_t)row * kvs + c4);
        }
        unsigned* dk = (unsigned*)&Ks[row * KST + c4];
        dk[0] = f2tf(kv.x); dk[1] = f2tf(kv.y); dk[2] = f2tf(kv.z); dk[3] = f2tf(kv.w);
        unsigned* dv = (unsigned*)&Vs[row * KST + c4];
        dv[0] = f2tf(vv.x); dv[1] = f2tf(vv.y); dv[2] = f2tf(vv.z); dv[3] = f2tf(vv.w);
    }
    __syncthreads();

    // ---- scores: warp computes m16 x n104 over k=64 ----
    const int n0 = wn * (NTJ * 8);
    float sc[NTJ][4];
    #pragma unroll
    for (int j = 0; j < NTJ; j++)
        #pragma unroll
        for (int t = 0; t < 4; t++) sc[j][t] = 0.f;

    const unsigned* Qu = (const unsigned*)Qs;
    const unsigned* Ku = (const unsigned*)Ks;
    const unsigned* Vu = (const unsigned*)Vs;

    #pragma unroll
    for (int kt = 0; kt < 8; kt++) {
        unsigned a[4];
        const unsigned* ap = Qu + (wm * 16 + r) * KST + kt * 8 + q;
        a[0] = ap[0];
        a[1] = ap[8 * KST];
        a[2] = ap[4];
        a[3] = ap[8 * KST + 4];
        #pragma unroll
        for (int j = 0; j < NTJ; j++) {
            unsigned b[2];
            const unsigned* bp = Ku + (n0 + j * 8 + r) * KST + kt * 8 + q;
            b[0] = bp[0];
            b[1] = bp[4];
            mma8(sc[j], a, b);
        }
    }

    // ---- scale + mask ----
    #pragma unroll
    for (int j = 0; j < NTJ; j++) {
        int cbase = n0 + j * 8 + 2 * q;
        #pragma unroll
        for (int t = 0; t < 4; t++) {
            int col = cbase + (t & 1);
            sc[j][t] = (col < NN) ? sc[j][t] * ATTN_SCALE : -1e30f;
        }
    }

    // ---- row max (half), cross-half via smem ----
    float mx0 = -1e30f, mx1 = -1e30f;
    #pragma unroll
    for (int j = 0; j < NTJ; j++) {
        mx0 = fmaxf(mx0, fmaxf(sc[j][0], sc[j][1]));
        mx1 = fmaxf(mx1, fmaxf(sc[j][2], sc[j][3]));
    }
    mx0 = fmaxf(mx0, __shfl_xor_sync(0xffffffffu, mx0, 1));
    mx0 = fmaxf(mx0, __shfl_xor_sync(0xffffffffu, mx0, 2));
    mx1 = fmaxf(mx1, __shfl_xor_sync(0xffffffffu, mx1, 1));
    mx1 = fmaxf(mx1, __shfl_xor_sync(0xffffffffu, mx1, 2));
    int rowl = wm * 16 + r;
    if (q == 0) {
        redmax[wn * 64 + rowl] = mx0;
        redmax[wn * 64 + rowl + 8] = mx1;
    }
    __syncthreads();   // also: all K/Q reads done -> Ps region reusable
    float fm0 = fmaxf(redmax[rowl], redmax[64 + rowl]);
    float fm1 = fmaxf(redmax[rowl + 8], redmax[64 + rowl + 8]);

    // ---- exp, row sum, write P (tf32) ----
    float s0 = 0.f, s1 = 0.f;
    #pragma unroll
    for (int j = 0; j < NTJ; j++) {
        sc[j][0] = __expf(sc[j][0] - fm0);
        sc[j][1] = __expf(sc[j][1] - fm0);
        sc[j][2] = __expf(sc[j][2] - fm1);
        sc[j][3] = __expf(sc[j][3] - fm1);
        s0 += sc[j][0] + sc[j][1];
        s1 += sc[j][2] + sc[j][3];
    }
    s0 += __shfl_xor_sync(0xffffffffu, s0, 1);
    s0 += __shfl_xor_sync(0xffffffffu, s0, 2);
    s1 += __shfl_xor_sync(0xffffffffu, s1, 1);
    s1 += __shfl_xor_sync(0xffffffffu, s1, 2);
    if (q == 0) {
        redsum[wn * 64 + rowl] = s0;
        redsum[wn * 64 + rowl + 8] = s1;
    }
    #pragma unroll
    for (int j = 0; j < NTJ; j++) {
        int cbase = n0 + j * 8 + 2 * q;
        unsigned* p0 = (unsigned*)&Ps[rowl * PST + cbase];
        unsigned* p1 = (unsigned*)&Ps[(rowl + 8) * PST + cbase];
        p0[0] = f2tf(sc[j][0]); p0[1] = f2tf(sc[j][1]);
        p1[0] = f2tf(sc[j][2]); p1[1] = f2tf(sc[j][3]);
    }
    __syncthreads();

    // ---- O = P @ V : warp computes m16 x n32 over k=208 ----
    const int oc0 = wn * 32;
    float oacc[4][4];
    #pragma unroll
    for (int j = 0; j < 4; j++)
        #pragma unroll
        for (int t = 0; t < 4; t++) oacc[j][t] = 0.f;

    const unsigned* Pu = (const unsigned*)Ps;
    #pragma unroll 2
    for (int kt = 0; kt < KP / 8; kt++) {
        unsigned a[4];
        const unsigned* ap = Pu + (wm * 16 + r) * PST + kt * 8 + q;
        a[0] = ap[0];
        a[1] = ap[8 * PST];
        a[2] = ap[4];
        a[3] = ap[8 * PST + 4];
        #pragma unroll
        for (int j = 0; j < 4; j++) {
            unsigned b[2];
            const unsigned* bp = Vu + (kt * 8 + q) * KST + oc0 + j * 8 + r;
            b[0] = bp[0];
            b[1] = bp[4 * KST];
            mma8(oacc[j], a, b);
        }
    }

    // ---- store O, scaled by 1/rowsum ----
    float inv0 = 1.0f / (redsum[rowl] + redsum[64 + rowl]);
    float inv1 = 1.0f / (redsum[rowl + 8] + redsum[64 + rowl + 8]);
    int mg0 = m0 + rowl, mg1 = m0 + rowl + 8;
    #pragma unroll
    for (int j = 0; j < 4; j++) {
        int col = oc0 + j * 8 + 2 * q;
        if (mg0 < NN)
            *(float2*)(op + (size_t)mg0 * CC + col) =
                make_float2(oacc[j][0] * inv0, oacc[j][1] * inv0);
        if (mg1 < NN)
            *(float2*)(op + (size_t)mg1 * CC + col) =
                make_float2(oacc[j][2] * inv1, oacc[j][3] * inv1);
    }
}

// ------------------------------- launch -------------------------------------
extern "C" void kernel_launch(void* const* d_in, const int* in_sizes, int n_in,
                              void* d_out, int out_size) {
    int sh = (in_sizes[5] == 1) ? 0 : -1;

    const float* xs  = (const float*)d_in[0];
    const float* ys  = (const float*)d_in[1];
    const int* rel   = (const int*)d_in[4];
    const float* qkv_w = (const float*)d_in[6 + sh];
    const float* ap_w  = (const float*)d_in[7 + sh];
    const float* ap_b  = (const float*)d_in[8 + sh];
    const float* q_w   = (const float*)d_in[9 + sh];
    const float* k_w   = (const float*)d_in[10 + sh];
    const float* v_w   = (const float*)d_in[11 + sh];
    const float* cp_w  = (const float*)d_in[12 + sh];
    const float* cp_b  = (const float*)d_in[13 + sh];
    const float* fc1_w = (const float*)d_in[14 + sh];
    const float* fc1_b = (const float*)d_in[15 + sh];
    const float* fc2_w = (const float*)d_in[16 + sh];
    const float* fc2_b = (const float*)d_in[17 + sh];
    const float* ln1w = (const float*)d_in[18 + sh];
    const float* ln1b = (const float*)d_in[19 + sh];
    const float* ln2w = (const float*)d_in[20 + sh];
    const float* ln2b = (const float*)d_in[21 + sh];
    const float* ln3w = (const float*)d_in[22 + sh];
    const float* ln3b = (const float*)d_in[23 + sh];
    const float* lnyw = (const float*)d_in[24 + sh];
    const float* lnyb = (const float*)d_in[25 + sh];
    float* out = (float*)d_out;

    float *x, *h, *yn, *qkv, *q, *k, *v, *o, *big, *big2;
    cudaGetSymbolAddress((void**)&x, g_x);
    cudaGetSymbolAddress((void**)&h, g_h);
    cudaGetSymbolAddress((void**)&yn, g_yn);
    cudaGetSymbolAddress((void**)&qkv, g_qkv);
    cudaGetSymbolAddress((void**)&q, g_q);
    cudaGetSymbolAddress((void**)&k, g_k);
    cudaGetSymbolAddress((void**)&v, g_v);
    cudaGetSymbolAddress((void**)&o, g_o);
    cudaGetSymbolAddress((void**)&big, g_big);
    cudaGetSymbolAddress((void**)&big2, g_big2);

    cudaFuncSetAttribute(gemm_tf32<0>, cudaFuncAttributeMaxDynamicSharedMemorySize, GEMM_SMEM);
    cudaFuncSetAttribute(gemm_tf32<1>, cudaFuncAttributeMaxDynamicSharedMemorySize, GEMM_SMEM);
    cudaFuncSetAttribute(gemm_tf32<2>, cudaFuncAttributeMaxDynamicSharedMemorySize, GEMM_SMEM);
    cudaFuncSetAttribute(gemm_tf32<3>, cudaFuncAttributeMaxDynamicSharedMemorySize, GEMM_SMEM);
    cudaFuncSetAttribute(attn_mma<false>, cudaFuncAttributeMaxDynamicSharedMemorySize, ATTN_SMEM);
    cudaFuncSetAttribute(attn_mma<true>,  cudaFuncAttributeMaxDynamicSharedMemorySize, ATTN_SMEM);

    copy_kernel<<<(T * CC + 255) / 256, 256>>>(xs, x, T * CC);

    // ---- self attention ----
    layernorm_kernel<<<T, 256>>>(x, ln1w, ln1b, h);
    gemm_tf32<0><<<dim3(3 * CC / 128, T / 128), 256, GEMM_SMEM>>>(h, qkv_w, nullptr, nullptr, qkv, T, 3 * CC, CC);
    attn_mma<false><<<dim3(4, PSELF), 256, ATTN_SMEM>>>(qkv, qkv, qkv, nullptr, o);
    gemm_tf32<2><<<dim3(CC / 128, T / 128), 256, GEMM_SMEM>>>(o, ap_w, ap_b, x, x, T, CC, CC);

    // ---- cross attention ----
    layernorm_kernel<<<T, 256>>>(x, ln2w, ln2b, h);
    layernorm_kernel<<<T, 256>>>(ys, lnyw, lnyb, yn);
    gemm_tf32<0><<<dim3(CC / 128, T / 128), 256, GEMM_SMEM>>>(h, q_w, nullptr, nullptr, q, T, CC, CC);
    gemm_tf32<0><<<dim3(CC / 128, T / 128), 256, GEMM_SMEM>>>(yn, k_w, nullptr, nullptr, k, T, CC, CC);
    gemm_tf32<0><<<dim3(CC / 128, T / 128), 256, GEMM_SMEM>>>(yn, v_w, nullptr, nullptr, v, T, CC, CC);
    attn_mma<true><<<dim3(4, PCROSS), 256, ATTN_SMEM>>>(q, k, v, rel, big);
    gemm_tf32<1><<<dim3(CC / 128, TT / 128), 256, GEMM_SMEM>>>(big, cp_w, cp_b, nullptr, big2, TT, CC, CC);
    merge_kernel<<<(T * CC + 255) / 256, 256>>>(big2, x);

    // ---- MLP ----
    layernorm_kernel<<<T, 256>>>(x, ln3w, ln3b, h);
    gemm_tf32<3><<<dim3(HID / 128, T / 128), 256, GEMM_SMEM>>>(h, fc1_w, fc1_b, nullptr, big2, T, HID, CC);
    gemm_tf32<2><<<dim3(CC / 128, T / 128), 256, GEMM_SMEM>>>(big2, fc2_w, fc2_b, x, out, T, CC, HID);
}